// round 7
// baseline (speedup 1.0000x reference)
#include <cuda_runtime.h>
#include <math.h>

#define BB   64
#define NCC  20
#define KK   150
#define CC   2048
#define C4   (CC/4)
#define TL   750
#define T_NCE 0.07f
#define EPSF  1e-7f
#define TOTB 512

// ---------------- scratch (device globals; unique writer per slot) ----------------------
__device__ float4 g_Sp [4][2][BB*C4];   // phase1: K-chunk partial column sums of HA/HB
__device__ float4 g_SEp[8][2][BB*C4];   // phase2: K-chunk partial column sums of EB/EA
__device__ float  g_dot[2][BB*KK];      // raw S_i . e_k
__device__ float  g_nrm[2][BB*KK];      // ||e_k||^2
__device__ float  g_nce[2*BB];
__device__ float  g_cls;
__device__ float  g_rel[8][2];
__device__ float  g_actw[TL];
__device__ float  g_acts[TL];
__device__ unsigned g_bar1 = 0, g_bar2 = 0, g_ctr = 0;   // reset by final block each replay

__device__ __forceinline__ void grid_barrier(unsigned* bar) {
    __threadfence();
    __syncthreads();
    if (threadIdx.x == 0) {
        atomicAdd(bar, 1u);
        volatile unsigned* p = bar;
        while (*p < TOTB) __nanosleep(64);
    }
    __syncthreads();
    __threadfence();
}

__global__ void __launch_bounds__(256, 4) fused(
    const float* __restrict__ HA, const float* __restrict__ HB,
    const float* __restrict__ EA, const float* __restrict__ EB,
    const float* __restrict__ vs, const float* __restrict__ lab,
    const float* __restrict__ rs, const float* __restrict__ rd,
    const float* __restrict__ a0, const float* __restrict__ a2,
    const float* __restrict__ att, float* __restrict__ out)
{
    int bx = blockIdx.x, tid = threadIdx.x;
    int wid = tid >> 5, lane = tid & 31;
    __shared__ float sd[19][8], sn[19][8];
    __shared__ float smg[8][4];
    __shared__ float bc[2];

    // ================= PHASE 1: stream HA,HB -> g_Sp ; misc losses =================
#pragma unroll
    for (int u = 0; u < 2; ++u) {
        int unit = bx + u * TOTB;               // 0..1023
        int t = unit >> 9, rem = unit & 511;
        int n = rem >> 3, ct = (rem >> 2) & 1, ks = rem & 3;
        int k0 = (ks * KK) >> 2, k1e = ((ks + 1) * KK) >> 2;
        int c4 = ct * 256 + tid;
        const float4* src = (const float4*)(t ? HB : HA) + (size_t)(n * KK + k0) * C4 + c4;
        float4 sa = make_float4(0.f,0.f,0.f,0.f), sb = sa, sc = sa, se = sa;
        int k = k0;
        for (; k + 3 < k1e; k += 4) {
            float4 e0 = __ldcs(src);            src += C4;
            float4 e1 = __ldcs(src);            src += C4;
            float4 e2 = __ldcs(src);            src += C4;
            float4 e3 = __ldcs(src);            src += C4;
            sa.x += e0.x; sa.y += e0.y; sa.z += e0.z; sa.w += e0.w;
            sb.x += e1.x; sb.y += e1.y; sb.z += e1.z; sb.w += e1.w;
            sc.x += e2.x; sc.y += e2.y; sc.z += e2.z; sc.w += e2.w;
            se.x += e3.x; se.y += e3.y; se.z += e3.z; se.w += e3.w;
        }
        for (; k < k1e; ++k) {
            float4 e0 = __ldcs(src);            src += C4;
            sa.x += e0.x; sa.y += e0.y; sa.z += e0.z; sa.w += e0.w;
        }
        sa.x += sb.x + sc.x + se.x;
        sa.y += sb.y + sc.y + se.y;
        sa.z += sb.z + sc.z + se.z;
        sa.w += sb.w + sc.w + se.w;
        g_Sp[ks][t][n * C4 + c4] = sa;
    }

    // misc riders
    if (bx == 0) {
        __shared__ float rowsum[BB];
        if (tid < BB) {
            float s = 0.f;
            for (int c = 0; c < NCC; ++c) s += lab[tid * NCC + c];
            rowsum[tid] = s;
        }
        __syncthreads();
        float acc = 0.f;
        for (int e = tid; e < BB * NCC; e += 256) {
            int n = e / NCC;
            float l = lab[e] / rowsum[n];
            float v = fminf(fmaxf(vs[e], EPSF), 1.f - EPSF);
            acc += l * logf(v) + (1.f - l) * log1pf(-v);
        }
        for (int o = 16; o; o >>= 1) acc += __shfl_down_sync(~0u, acc, o);
        if (lane == 0) smg[wid][0] = acc;
        __syncthreads();
        if (tid == 0) {
            float t2 = 0.f;
            for (int w = 0; w < 8; ++w) t2 += smg[w][0];
            g_cls = t2;
        }
        __syncthreads();
    } else if (bx <= 8) {
        int blk = bx - 1;
        float ss = 0.f, sdd = 0.f;
        for (int e = blk * 256 + tid; e < 2 * BB * TL; e += 8 * 256) {
            float a = 1.f - rs[e]; ss += a * a;
            float b = rd[e];       sdd += b * b;
        }
        for (int o = 16; o; o >>= 1) {
            ss  += __shfl_down_sync(~0u, ss,  o);
            sdd += __shfl_down_sync(~0u, sdd, o);
        }
        if (lane == 0) { smg[wid][0] = ss; smg[wid][1] = sdd; }
        __syncthreads();
        if (tid == 0) {
            float S = 0.f, D = 0.f;
            for (int w = 0; w < 8; ++w) { S += smg[w][0]; D += smg[w][1]; }
            g_rel[blk][0] = S; g_rel[blk][1] = D;
        }
        __syncthreads();
    } else if (bx < 9 + 188) {
        // loss_act: 4 time-steps per block; 64 lanes = batch
        __shared__ float smq[4][2], sma2[4][2];
        int tg = tid >> 6;
        int b  = tid & 63;
        int hf = (tid >> 5) & 1;
        int t  = (bx - 9) * 4 + tg;
        bool valid = t < TL;
        float a0t = valid ? a0[b * TL + t] : 0.f;
        float a2t = valid ? a2[b * TL + t] : 0.f;
        float local = 0.f;
        for (int j = 0; j < 11; ++j) {
            float sq = 0.f, ab = 0.f;
            if (valid) {
                int c = t + j - 6; c = c < 0 ? 0 : (c > TL - 1 ? TL - 1 : c);
                float d0 = a0t - a0[b * TL + c]; sq = d0 * d0;
                ab = fabsf(a2t - a2[b * TL + c]);
            }
            for (int o = 16; o; o >>= 1) {
                sq += __shfl_down_sync(~0u, sq, o);
                ab += __shfl_down_sync(~0u, ab, o);
            }
            if (lane == 0) { smq[tg][hf] = sq; sma2[tg][hf] = ab; }
            __syncthreads();
            if ((tid & 63) == 0) {
                float SQ = smq[tg][0] + smq[tg][1];
                float AB = sma2[tg][0] + sma2[tg][1];
                local += expf(-0.5f * SQ) * (AB * (1.f / BB));
            }
            __syncthreads();
        }
        if ((tid & 63) == 0 && valid) g_actw[t] = local;
        float d = valid ? (a0t - a2t) * (a0t - a2t) : 0.f;
        for (int o = 16; o; o >>= 1) d += __shfl_down_sync(~0u, d, o);
        if (lane == 0) smq[tg][hf] = d;
        __syncthreads();
        if ((tid & 63) == 0 && valid) g_acts[t] = smq[tg][0] + smq[tg][1];
        __syncthreads();
    }

    grid_barrier(&g_bar1);

    // ================= PHASE 2: stream EA,EB -> dots, norms, SE partials ============
#pragma unroll
    for (int u = 0; u < 2; ++u) {
        int unit = bx + u * TOTB;               // 0..1023
        int i = unit >> 9, rem = unit & 511;
        int n = rem >> 3, ks = rem & 7;
        int k0 = (ks * KK) >> 3, k1e = ((ks + 1) * KK) >> 3;
        int cnt = k1e - k0;

        float4 q0 = make_float4(0.f,0.f,0.f,0.f), q1 = q0;
#pragma unroll
        for (int p = 0; p < 4; ++p) {
            float4 a = g_Sp[p][i][n * C4 + tid];
            float4 b = g_Sp[p][i][n * C4 + 256 + tid];
            q0.x += a.x; q0.y += a.y; q0.z += a.z; q0.w += a.w;
            q1.x += b.x; q1.y += b.y; q1.z += b.z; q1.w += b.w;
        }

        const float4* src = (const float4*)(i ? EA : EB) + (size_t)(n * KK + k0) * C4;
        float4 s0 = make_float4(0.f,0.f,0.f,0.f), s1 = s0;

        float4 e0 = __ldcs(src + tid);
        float4 e1 = __ldcs(src + 256 + tid);
        src += C4;
        for (int k = 0; k < cnt; ++k) {
            float4 f0, f1;
            if (k + 1 < cnt) {
                f0 = __ldcs(src + tid);
                f1 = __ldcs(src + 256 + tid);
                src += C4;
            }
            s0.x += e0.x; s0.y += e0.y; s0.z += e0.z; s0.w += e0.w;
            s1.x += e1.x; s1.y += e1.y; s1.z += e1.z; s1.w += e1.w;
            float d  = q0.x*e0.x + q0.y*e0.y + q0.z*e0.z + q0.w*e0.w
                     + q1.x*e1.x + q1.y*e1.y + q1.z*e1.z + q1.w*e1.w;
            float nn = e0.x*e0.x + e0.y*e0.y + e0.z*e0.z + e0.w*e0.w
                     + e1.x*e1.x + e1.y*e1.y + e1.z*e1.z + e1.w*e1.w;
            for (int o = 16; o; o >>= 1) {
                d  += __shfl_down_sync(~0u, d,  o);
                nn += __shfl_down_sync(~0u, nn, o);
            }
            if (lane == 0) { sd[k][wid] = d; sn[k][wid] = nn; }
            e0 = f0; e1 = f1;
        }
        __syncthreads();
        if (tid < cnt) {
            float D = 0.f;
#pragma unroll
            for (int w = 0; w < 8; ++w) D += sd[tid][w];
            g_dot[i][n * KK + k0 + tid] = D;
        } else if (tid >= 64 && tid < 64 + cnt) {
            int kk = tid - 64;
            float N = 0.f;
#pragma unroll
            for (int w = 0; w < 8; ++w) N += sn[kk][w];
            g_nrm[i][n * KK + k0 + kk] = N;
        }
        g_SEp[ks][i][n * C4 + tid] = s0;
        g_SEp[ks][i][n * C4 + 256 + tid] = s1;
        __syncthreads();
    }

    grid_barrier(&g_bar2);

    // ================= PHASE 3: NCE softmax per (i,n) on blocks 0..127 ==============
    if (bx >= 128) return;
    {
        int i = bx >> 6, n = bx & 63;

        float4 S0 = make_float4(0.f,0.f,0.f,0.f), S1 = S0, E0 = S0, E1 = S0;
#pragma unroll
        for (int p = 0; p < 4; ++p) {
            float4 a = g_Sp[p][i][n * C4 + tid];
            float4 b = g_Sp[p][i][n * C4 + 256 + tid];
            S0.x += a.x; S0.y += a.y; S0.z += a.z; S0.w += a.w;
            S1.x += b.x; S1.y += b.y; S1.z += b.z; S1.w += b.w;
        }
#pragma unroll
        for (int p = 0; p < 8; ++p) {
            float4 a = g_SEp[p][1 - i][n * C4 + tid];
            float4 b = g_SEp[p][1 - i][n * C4 + 256 + tid];
            E0.x += a.x; E0.y += a.y; E0.z += a.z; E0.w += a.w;
            E1.x += b.x; E1.y += b.y; E1.z += b.z; E1.w += b.w;
        }
        float qss  = S0.x*S0.x+S0.y*S0.y+S0.z*S0.z+S0.w*S0.w + S1.x*S1.x+S1.y*S1.y+S1.z*S1.z+S1.w*S1.w;
        float sess = E0.x*E0.x+E0.y*E0.y+E0.z*E0.z+E0.w*E0.w + E1.x*E1.x+E1.y*E1.y+E1.z*E1.z+E1.w*E1.w;
        float dse  = S0.x*E0.x+S0.y*E0.y+S0.z*E0.z+S0.w*E0.w + S1.x*E1.x+S1.y*E1.y+S1.z*E1.z+S1.w*E1.w;

        for (int o = 16; o; o >>= 1) {
            qss  += __shfl_down_sync(~0u, qss,  o);
            sess += __shfl_down_sync(~0u, sess, o);
            dse  += __shfl_down_sync(~0u, dse,  o);
        }
        if (lane == 0) { smg[wid][0] = qss; smg[wid][1] = sess; smg[wid][2] = dse; }
        __syncthreads();
        if (tid == 0) {
            float Q = 0.f, S = 0.f, D = 0.f;
            for (int w = 0; w < 8; ++w) { Q += smg[w][0]; S += smg[w][1]; D += smg[w][2]; }
            float rq = rsqrtf(Q);
            bc[0] = rq;
            bc[1] = D * rq * rsqrtf(S) * (1.f / T_NCE);   // logit0
        }
        __syncthreads();
        float rq = bc[0], logit0 = bc[1];

        float logit = -1e30f;
        if (tid == 0) logit = logit0;
        else if (tid <= 150) {
            int k = tid - 1;
            logit = att[n * 300 + i * 150 + k] * g_dot[i][n * KK + k] * rq
                  * rsqrtf(g_nrm[i][n * KK + k]) * (1.f / T_NCE);
        }
        float mx = logit;
        for (int o = 16; o; o >>= 1) mx = fmaxf(mx, __shfl_xor_sync(~0u, mx, o));
        if (lane == 0) smg[wid][0] = mx;
        __syncthreads();
        if (tid == 0) {
            float M = -1e30f;
            for (int w = 0; w < 8; ++w) M = fmaxf(M, smg[w][0]);
            bc[0] = M;
        }
        __syncthreads();
        float M = bc[0];
        float ex = (tid <= 150) ? expf(logit - M) : 0.f;
        for (int o = 16; o; o >>= 1) ex += __shfl_down_sync(~0u, ex, o);
        if (lane == 0) smg[wid][1] = ex;
        __syncthreads();
        if (tid == 0) {
            float SE = 0.f;
            for (int w = 0; w < 8; ++w) SE += smg[w][1];
            g_nce[i * 64 + n] = logf(SE) + M - logit0;
        }
    }

    // ---- last-of-128 combine ----
    __shared__ unsigned lastf;
    __threadfence();
    __syncthreads();
    if (tid == 0) lastf = (atomicAdd(&g_ctr, 1u) == 127u) ? 1u : 0u;
    __syncthreads();
    if (!lastf) return;
    __threadfence();

    float sn2 = 0.f, sw = 0.f, ss = 0.f, sr = 0.f;
    for (int e = tid; e < 2 * BB; e += 256) sn2 += g_nce[e];
    for (int e = tid; e < TL; e += 256) { sw += g_actw[e]; ss += g_acts[e]; }
    if (tid < 16) sr = g_rel[tid >> 1][tid & 1];
    for (int o = 16; o; o >>= 1) {
        sn2 += __shfl_down_sync(~0u, sn2, o);
        sw  += __shfl_down_sync(~0u, sw,  o);
        ss  += __shfl_down_sync(~0u, ss,  o);
        sr  += __shfl_down_sync(~0u, sr,  o);
    }
    if (lane == 0) { smg[wid][0]=sn2; smg[wid][1]=sw; smg[wid][2]=ss; smg[wid][3]=sr; }
    __syncthreads();
    if (tid == 0) {
        float SN=0.f, SW=0.f, SS=0.f, SR=0.f;
        for (int w = 0; w < 8; ++w) { SN+=smg[w][0]; SW+=smg[w][1]; SS+=smg[w][2]; SR+=smg[w][3]; }
        float cls   = -g_cls * (1.f / (BB * NCC));
        float rel   = SR * (1.f / (2 * BB * TL));
        float act   = SW + 0.1f * SS * (1.f / BB);
        float snico = SN * (1.f / BB);
        out[0] = cls + 0.01f * snico + act + 0.1f * rel;
        out[1] = cls; out[2] = snico; out[3] = act; out[4] = rel;
        g_bar1 = 0; g_bar2 = 0; g_ctr = 0;            // reset for next graph replay
    }
}

extern "C" void kernel_launch(void* const* d_in, const int* in_sizes, int n_in,
                              void* d_out, int out_size) {
    const float* video = (const float*)d_in[0];
    const float* label = (const float*)d_in[1];
    const float* HA    = (const float*)d_in[2];
    const float* EA    = (const float*)d_in[3];
    const float* HB    = (const float*)d_in[4];
    const float* EB    = (const float*)d_in[5];
    const float* rs    = (const float*)d_in[6];
    const float* rd    = (const float*)d_in[7];
    const float* a0    = (const float*)d_in[8];
    const float* a2    = (const float*)d_in[9];
    const float* att   = (const float*)d_in[10];
    float* out = (float*)d_out;

    fused<<<TOTB, 256>>>(HA, HB, EA, EB, video, label, rs, rd, a0, a2, att, out);
    (void)in_sizes; (void)n_in; (void)out_size;
}

// round 8
// speedup vs baseline: 1.0281x; 1.0281x over previous
#include <cuda_runtime.h>
#include <math.h>

#define BB   64
#define NCC  20
#define KK   150
#define CC   2048
#define C4   (CC/4)
#define TL   750
#define T_NCE 0.07f
#define EPSF  1e-7f
#define TOTB 512

// ---------------- scratch (device globals; unique writer per slot) ----------------------
__device__ float4 g_Sp [4][2][BB*C4];   // phase1: K-chunk partial column sums of HA/HB
__device__ float4 g_SEp[8][2][BB*C4];   // phase2: K-chunk partial column sums of EB/EA
__device__ float  g_dot[2][BB*KK];      // raw S_i . e_k
__device__ float  g_nrm[2][BB*KK];      // ||e_k||^2
__device__ float  g_nce[2*BB];
__device__ float  g_cls;
__device__ float  g_rel[8][2];
__device__ float  g_actw[TL];
__device__ float  g_acts[TL];
__device__ unsigned g_bar1 = 0, g_bar2 = 0, g_ctr = 0;   // reset by final block each replay

__device__ __forceinline__ void grid_barrier(unsigned* bar) {
    __threadfence();
    __syncthreads();
    if (threadIdx.x == 0) {
        atomicAdd(bar, 1u);
        volatile unsigned* p = bar;
        while (*p < TOTB) __nanosleep(64);
    }
    __syncthreads();
    __threadfence();
}

__global__ void __launch_bounds__(256, 4) fused(
    const float* __restrict__ HA, const float* __restrict__ HB,
    const float* __restrict__ EA, const float* __restrict__ EB,
    const float* __restrict__ vs, const float* __restrict__ lab,
    const float* __restrict__ rs, const float* __restrict__ rd,
    const float* __restrict__ a0, const float* __restrict__ a2,
    const float* __restrict__ att, float* __restrict__ out)
{
    int bx = blockIdx.x, tid = threadIdx.x;
    int wid = tid >> 5, lane = tid & 31;
    __shared__ float sd[19][8], sn[19][8];
    __shared__ float smg[8][4];
    __shared__ float bc[2];

    // ================= PHASE 1: stream HA,HB -> g_Sp ; misc losses =================
#pragma unroll
    for (int u = 0; u < 2; ++u) {
        int unit = bx + u * TOTB;               // 0..1023
        int t = unit >> 9, rem = unit & 511;
        int n = rem >> 3, ct = (rem >> 2) & 1, ks = rem & 3;
        int k0 = (ks * KK) >> 2, k1e = ((ks + 1) * KK) >> 2;
        int c4 = ct * 256 + tid;
        const float4* src = (const float4*)(t ? HB : HA) + (size_t)(n * KK + k0) * C4 + c4;
        float4 sa = make_float4(0.f,0.f,0.f,0.f), sb = sa, sc = sa, se = sa;
        int k = k0;
        for (; k + 3 < k1e; k += 4) {
            float4 e0 = __ldcs(src);            src += C4;
            float4 e1 = __ldcs(src);            src += C4;
            float4 e2 = __ldcs(src);            src += C4;
            float4 e3 = __ldcs(src);            src += C4;
            sa.x += e0.x; sa.y += e0.y; sa.z += e0.z; sa.w += e0.w;
            sb.x += e1.x; sb.y += e1.y; sb.z += e1.z; sb.w += e1.w;
            sc.x += e2.x; sc.y += e2.y; sc.z += e2.z; sc.w += e2.w;
            se.x += e3.x; se.y += e3.y; se.z += e3.z; se.w += e3.w;
        }
        for (; k < k1e; ++k) {
            float4 e0 = __ldcs(src);            src += C4;
            sa.x += e0.x; sa.y += e0.y; sa.z += e0.z; sa.w += e0.w;
        }
        sa.x += sb.x + sc.x + se.x;
        sa.y += sb.y + sc.y + se.y;
        sa.z += sb.z + sc.z + se.z;
        sa.w += sb.w + sc.w + se.w;
        g_Sp[ks][t][n * C4 + c4] = sa;
    }

    // misc riders
    if (bx == 0) {
        __shared__ float rowsum[BB];
        if (tid < BB) {
            float s = 0.f;
            for (int c = 0; c < NCC; ++c) s += lab[tid * NCC + c];
            rowsum[tid] = s;
        }
        __syncthreads();
        float acc = 0.f;
        for (int e = tid; e < BB * NCC; e += 256) {
            int n = e / NCC;
            float l = lab[e] / rowsum[n];
            float v = fminf(fmaxf(vs[e], EPSF), 1.f - EPSF);
            acc += l * logf(v) + (1.f - l) * log1pf(-v);
        }
        for (int o = 16; o; o >>= 1) acc += __shfl_down_sync(~0u, acc, o);
        if (lane == 0) smg[wid][0] = acc;
        __syncthreads();
        if (tid == 0) {
            float t2 = 0.f;
            for (int w = 0; w < 8; ++w) t2 += smg[w][0];
            g_cls = t2;
        }
        __syncthreads();
    } else if (bx <= 8) {
        int blk = bx - 1;
        float ss = 0.f, sdd = 0.f;
        for (int e = blk * 256 + tid; e < 2 * BB * TL; e += 8 * 256) {
            float a = 1.f - rs[e]; ss += a * a;
            float b = rd[e];       sdd += b * b;
        }
        for (int o = 16; o; o >>= 1) {
            ss  += __shfl_down_sync(~0u, ss,  o);
            sdd += __shfl_down_sync(~0u, sdd, o);
        }
        if (lane == 0) { smg[wid][0] = ss; smg[wid][1] = sdd; }
        __syncthreads();
        if (tid == 0) {
            float S = 0.f, D = 0.f;
            for (int w = 0; w < 8; ++w) { S += smg[w][0]; D += smg[w][1]; }
            g_rel[blk][0] = S; g_rel[blk][1] = D;
        }
        __syncthreads();
    } else if (bx < 9 + 188) {
        // loss_act: 4 time-steps per block; 64 lanes = batch
        __shared__ float smq[4][2], sma2[4][2];
        int tg = tid >> 6;
        int b  = tid & 63;
        int hf = (tid >> 5) & 1;
        int t  = (bx - 9) * 4 + tg;
        bool valid = t < TL;
        float a0t = valid ? a0[b * TL + t] : 0.f;
        float a2t = valid ? a2[b * TL + t] : 0.f;
        float local = 0.f;
        for (int j = 0; j < 11; ++j) {
            float sq = 0.f, ab = 0.f;
            if (valid) {
                int c = t + j - 6; c = c < 0 ? 0 : (c > TL - 1 ? TL - 1 : c);
                float d0 = a0t - a0[b * TL + c]; sq = d0 * d0;
                ab = fabsf(a2t - a2[b * TL + c]);
            }
            for (int o = 16; o; o >>= 1) {
                sq += __shfl_down_sync(~0u, sq, o);
                ab += __shfl_down_sync(~0u, ab, o);
            }
            if (lane == 0) { smq[tg][hf] = sq; sma2[tg][hf] = ab; }
            __syncthreads();
            if ((tid & 63) == 0) {
                float SQ = smq[tg][0] + smq[tg][1];
                float AB = sma2[tg][0] + sma2[tg][1];
                local += expf(-0.5f * SQ) * (AB * (1.f / BB));
            }
            __syncthreads();
        }
        if ((tid & 63) == 0 && valid) g_actw[t] = local;
        float d = valid ? (a0t - a2t) * (a0t - a2t) : 0.f;
        for (int o = 16; o; o >>= 1) d += __shfl_down_sync(~0u, d, o);
        if (lane == 0) smq[tg][hf] = d;
        __syncthreads();
        if ((tid & 63) == 0 && valid) g_acts[t] = smq[tg][0] + smq[tg][1];
        __syncthreads();
    }

    grid_barrier(&g_bar1);

    // ================= PHASE 2: stream EA,EB -> dots, norms, SE partials ============
#pragma unroll
    for (int u = 0; u < 2; ++u) {
        int unit = bx + u * TOTB;               // 0..1023
        int i = unit >> 9, rem = unit & 511;
        int n = rem >> 3, ks = rem & 7;
        int k0 = (ks * KK) >> 3, k1e = ((ks + 1) * KK) >> 3;
        int cnt = k1e - k0;

        float4 q0 = make_float4(0.f,0.f,0.f,0.f), q1 = q0;
#pragma unroll
        for (int p = 0; p < 4; ++p) {
            float4 a = g_Sp[p][i][n * C4 + tid];
            float4 b = g_Sp[p][i][n * C4 + 256 + tid];
            q0.x += a.x; q0.y += a.y; q0.z += a.z; q0.w += a.w;
            q1.x += b.x; q1.y += b.y; q1.z += b.z; q1.w += b.w;
        }

        const float4* src = (const float4*)(i ? EA : EB) + (size_t)(n * KK + k0) * C4;
        float4 s0 = make_float4(0.f,0.f,0.f,0.f), s1 = s0;

        float4 e0 = __ldcs(src + tid);
        float4 e1 = __ldcs(src + 256 + tid);
        src += C4;
        for (int k = 0; k < cnt; ++k) {
            float4 f0, f1;
            if (k + 1 < cnt) {
                f0 = __ldcs(src + tid);
                f1 = __ldcs(src + 256 + tid);
                src += C4;
            }
            s0.x += e0.x; s0.y += e0.y; s0.z += e0.z; s0.w += e0.w;
            s1.x += e1.x; s1.y += e1.y; s1.z += e1.z; s1.w += e1.w;
            float d  = q0.x*e0.x + q0.y*e0.y + q0.z*e0.z + q0.w*e0.w
                     + q1.x*e1.x + q1.y*e1.y + q1.z*e1.z + q1.w*e1.w;
            float nn = e0.x*e0.x + e0.y*e0.y + e0.z*e0.z + e0.w*e0.w
                     + e1.x*e1.x + e1.y*e1.y + e1.z*e1.z + e1.w*e1.w;
            for (int o = 16; o; o >>= 1) {
                d  += __shfl_down_sync(~0u, d,  o);
                nn += __shfl_down_sync(~0u, nn, o);
            }
            if (lane == 0) { sd[k][wid] = d; sn[k][wid] = nn; }
            e0 = f0; e1 = f1;
        }
        __syncthreads();
        if (tid < cnt) {
            float D = 0.f;
#pragma unroll
            for (int w = 0; w < 8; ++w) D += sd[tid][w];
            g_dot[i][n * KK + k0 + tid] = D;
        } else if (tid >= 64 && tid < 64 + cnt) {
            int kk = tid - 64;
            float N = 0.f;
#pragma unroll
            for (int w = 0; w < 8; ++w) N += sn[kk][w];
            g_nrm[i][n * KK + k0 + kk] = N;
        }
        g_SEp[ks][i][n * C4 + tid] = s0;
        g_SEp[ks][i][n * C4 + 256 + tid] = s1;
        __syncthreads();
    }

    grid_barrier(&g_bar2);

    // ================= PHASE 3: NCE softmax per (i,n) on blocks 0..127 ==============
    if (bx >= 128) return;
    {
        int i = bx >> 6, n = bx & 63;

        float4 S0 = make_float4(0.f,0.f,0.f,0.f), S1 = S0, E0 = S0, E1 = S0;
#pragma unroll
        for (int p = 0; p < 4; ++p) {
            float4 a = g_Sp[p][i][n * C4 + tid];
            float4 b = g_Sp[p][i][n * C4 + 256 + tid];
            S0.x += a.x; S0.y += a.y; S0.z += a.z; S0.w += a.w;
            S1.x += b.x; S1.y += b.y; S1.z += b.z; S1.w += b.w;
        }
#pragma unroll
        for (int p = 0; p < 8; ++p) {
            float4 a = g_SEp[p][1 - i][n * C4 + tid];
            float4 b = g_SEp[p][1 - i][n * C4 + 256 + tid];
            E0.x += a.x; E0.y += a.y; E0.z += a.z; E0.w += a.w;
            E1.x += b.x; E1.y += b.y; E1.z += b.z; E1.w += b.w;
        }
        float qss  = S0.x*S0.x+S0.y*S0.y+S0.z*S0.z+S0.w*S0.w + S1.x*S1.x+S1.y*S1.y+S1.z*S1.z+S1.w*S1.w;
        float sess = E0.x*E0.x+E0.y*E0.y+E0.z*E0.z+E0.w*E0.w + E1.x*E1.x+E1.y*E1.y+E1.z*E1.z+E1.w*E1.w;
        float dse  = S0.x*E0.x+S0.y*E0.y+S0.z*E0.z+S0.w*E0.w + S1.x*E1.x+S1.y*E1.y+S1.z*E1.z+S1.w*E1.w;

        for (int o = 16; o; o >>= 1) {
            qss  += __shfl_down_sync(~0u, qss,  o);
            sess += __shfl_down_sync(~0u, sess, o);
            dse  += __shfl_down_sync(~0u, dse,  o);
        }
        if (lane == 0) { smg[wid][0] = qss; smg[wid][1] = sess; smg[wid][2] = dse; }
        __syncthreads();
        if (tid == 0) {
            float Q = 0.f, S = 0.f, D = 0.f;
            for (int w = 0; w < 8; ++w) { Q += smg[w][0]; S += smg[w][1]; D += smg[w][2]; }
            float rq = rsqrtf(Q);
            bc[0] = rq;
            bc[1] = D * rq * rsqrtf(S) * (1.f / T_NCE);   // logit0
        }
        __syncthreads();
        float rq = bc[0], logit0 = bc[1];

        float logit = -1e30f;
        if (tid == 0) logit = logit0;
        else if (tid <= 150) {
            int k = tid - 1;
            logit = att[n * 300 + i * 150 + k] * g_dot[i][n * KK + k] * rq
                  * rsqrtf(g_nrm[i][n * KK + k]) * (1.f / T_NCE);
        }
        float mx = logit;
        for (int o = 16; o; o >>= 1) mx = fmaxf(mx, __shfl_xor_sync(~0u, mx, o));
        if (lane == 0) smg[wid][0] = mx;
        __syncthreads();
        if (tid == 0) {
            float M = -1e30f;
            for (int w = 0; w < 8; ++w) M = fmaxf(M, smg[w][0]);
            bc[0] = M;
        }
        __syncthreads();
        float M = bc[0];
        float ex = (tid <= 150) ? expf(logit - M) : 0.f;
        for (int o = 16; o; o >>= 1) ex += __shfl_down_sync(~0u, ex, o);
        if (lane == 0) smg[wid][1] = ex;
        __syncthreads();
        if (tid == 0) {
            float SE = 0.f;
            for (int w = 0; w < 8; ++w) SE += smg[w][1];
            g_nce[i * 64 + n] = logf(SE) + M - logit0;
        }
    }

    // ---- last-of-128 combine ----
    __shared__ unsigned lastf;
    __threadfence();
    __syncthreads();
    if (tid == 0) lastf = (atomicAdd(&g_ctr, 1u) == 127u) ? 1u : 0u;
    __syncthreads();
    if (!lastf) return;
    __threadfence();

    float sn2 = 0.f, sw = 0.f, ss = 0.f, sr = 0.f;
    for (int e = tid; e < 2 * BB; e += 256) sn2 += g_nce[e];
    for (int e = tid; e < TL; e += 256) { sw += g_actw[e]; ss += g_acts[e]; }
    if (tid < 16) sr = g_rel[tid >> 1][tid & 1];
    for (int o = 16; o; o >>= 1) {
        sn2 += __shfl_down_sync(~0u, sn2, o);
        sw  += __shfl_down_sync(~0u, sw,  o);
        ss  += __shfl_down_sync(~0u, ss,  o);
        sr  += __shfl_down_sync(~0u, sr,  o);
    }
    if (lane == 0) { smg[wid][0]=sn2; smg[wid][1]=sw; smg[wid][2]=ss; smg[wid][3]=sr; }
    __syncthreads();
    if (tid == 0) {
        float SN=0.f, SW=0.f, SS=0.f, SR=0.f;
        for (int w = 0; w < 8; ++w) { SN+=smg[w][0]; SW+=smg[w][1]; SS+=smg[w][2]; SR+=smg[w][3]; }
        float cls   = -g_cls * (1.f / (BB * NCC));
        float rel   = SR * (1.f / (2 * BB * TL));
        float act   = SW + 0.1f * SS * (1.f / BB);
        float snico = SN * (1.f / BB);
        out[0] = cls + 0.01f * snico + act + 0.1f * rel;
        out[1] = cls; out[2] = snico; out[3] = act; out[4] = rel;
        g_bar1 = 0; g_bar2 = 0; g_ctr = 0;            // reset for next graph replay
    }
}

extern "C" void kernel_launch(void* const* d_in, const int* in_sizes, int n_in,
                              void* d_out, int out_size) {
    const float* video = (const float*)d_in[0];
    const float* label = (const float*)d_in[1];
    const float* HA    = (const float*)d_in[2];
    const float* EA    = (const float*)d_in[3];
    const float* HB    = (const float*)d_in[4];
    const float* EB    = (const float*)d_in[5];
    const float* rs    = (const float*)d_in[6];
    const float* rd    = (const float*)d_in[7];
    const float* a0    = (const float*)d_in[8];
    const float* a2    = (const float*)d_in[9];
    const float* att   = (const float*)d_in[10];
    float* out = (float*)d_out;

    fused<<<TOTB, 256>>>(HA, HB, EA, EB, video, label, rs, rd, a0, a2, att, out);
    (void)in_sizes; (void)n_in; (void)out_size;
}